// round 8
// baseline (speedup 1.0000x reference)
#include <cuda_runtime.h>

// OT_Loss: batched Sinkhorn OT. B=128 images, N=1024 points, 16x16 grid, REG=10.
// Separable: K[n][j*16+i] = Ky[n][j]*Kx[n][i]. One block per image, 1024 threads.
// R8: u-pass handles 2 points/thread (halves Vs LDS traffic), wd epilogue
// 2 points/thread with z recomputed in-place, CONV_TOL 5e-3.

#define REGP     10.0f
#define TSTRIDE  1028          // floats; row shift 16B mod 128 per row
#define CONV_TOL 5e-3f
#define RHO      0.99687988f   // exp(-2*D^2/REG), D = 0.125
#define PSTRIDE  257           // partials stride (floats): conflict-free combine

typedef unsigned long long u64t;

__device__ __forceinline__ u64t pack2(float a, float b) {
    u64t r; asm("mov.b64 %0, {%1, %2};" : "=l"(r) : "f"(a), "f"(b)); return r;
}
__device__ __forceinline__ void unpack2(u64t v, float& a, float& b) {
    asm("mov.b64 {%0, %1}, %2;" : "=f"(a), "=f"(b) : "l"(v));
}
__device__ __forceinline__ void fma2(u64t& d, u64t a, u64t b) {
    asm("fma.rn.f32x2 %0, %1, %2, %0;" : "+l"(d) : "l"(a), "l"(b));
}
__device__ __forceinline__ u64t mul2(u64t a, u64t b) {
    u64t r; asm("mul.rn.f32x2 %0, %1, %2;" : "=l"(r) : "l"(a), "l"(b)); return r;
}
__device__ __forceinline__ float hsum1(u64t a) {
    float x, y; unpack2(a, x, y); return x + y;
}
__device__ __forceinline__ float hsum2(u64t a, u64t b) {
    float ax, ay, bx, by; unpack2(a, ax, ay); unpack2(b, bx, by);
    return (ax + ay) + (bx + by);
}

__device__ float        g_partial[128 * 3];
__device__ unsigned int g_ctr = 0;

__global__ void __launch_bounds__(1024, 1) ot_kernel(
    const float* __restrict__ nd,   // [128,256]
    const float* __restrict__ ud,   // [128,256]
    const float* __restrict__ pts,  // [128,1024,2]
    float* __restrict__ out)        // [3]
{
    extern __shared__ float sm[];
    float* KxT  = sm;                    // [16][TSTRIDE]
    float* KyT  = KxT  + 16 * TSTRIDE;
    float* us   = KyT  + 16 * TSTRIDE;   // [1024]
    float* Vs   = us   + 1024;           // [256]
    float* Vm1  = Vs   + 256;            // [256]
    float* bsh  = Vm1  + 256;            // [256]
    float* part = bsh  + 256;            // [32*PSTRIDE]
    float* red  = part + 32 * PSTRIDE;   // [64]
    __shared__ int s_conv, s_last;

    const int tid  = threadIdx.x;
    const int lane = tid & 31;
    const int wrp  = tid >> 5;
    const int img  = blockIdx.x;
    const float a_val = 1.0f / 1024.0f;

    float cood[16];
#pragma unroll
    for (int i = 0; i < 16; i++)
        cood[i] = (float)(16 * i + 8) * (1.0f / 256.0f) * 2.0f - 1.0f;

    if (tid < 256) { bsh[tid] = nd[img * 256 + tid]; Vs[tid] = 1.0f / 256.0f; }
    if (tid == 0) s_conv = 0;

    // ---- setup: one point per thread; kx/ky by geometric recurrence ----
    us[tid] = a_val;
    {
        float ppx = pts[img * 2048 + 2 * tid]     * (2.0f / 256.0f) - 1.0f;
        float ppy = pts[img * 2048 + 2 * tid + 1] * (2.0f / 256.0f) - 1.0f;
        float dx0 = ppx - cood[0];
        float dy0 = ppy - cood[0];
        float kx = __expf(dx0 * dx0 * (-1.0f / REGP));
        float ky = __expf(dy0 * dy0 * (-1.0f / REGP));
        float rx = __expf((0.25f * dx0 - 0.015625f) * (1.0f / REGP));
        float ry = __expf((0.25f * dy0 - 0.015625f) * (1.0f / REGP));
#pragma unroll
        for (int i = 0; i < 16; i++) {
            KxT[i * TSTRIDE + tid] = kx;
            KyT[i * TSTRIDE + tid] = ky;
            kx *= rx; rx *= RHO;
            ky *= ry; ry *= RHO;
        }
    }
    __syncthreads();

    // v-pass mapping: thread = (hh, jg, ig); 4x4 cells {jg+4r}x{ig+4c},
    // n-chunk hh covers floats [hh*16, hh*16+16). Warp holds hh={2w,2w+1}.
    const int hh = tid >> 4;          // 0..63
    const int jg = (tid >> 2) & 3;    // 0..3
    const int ig = tid & 3;           // 0..3
    const float* kyb = KyT + jg * TSTRIDE + hh * 16;
    const float* kxb = KxT + ig * TSTRIDE + hh * 16;
    const float* ub  = us + hh * 16;
    const int m_off  = ((tid >> 4) & 1) * 2;   // which c-pair this lane stores

    // combine-phase mapping: 4 threads per cell; each sums 8 of 32 chunk-partials
    const int cc = tid >> 2, qd = tid & 3;
    const float* pbase = part + qd * 8 * PSTRIDE + cc;

    // u-pass: thread t<512 owns points (2t, 2t+1); un pair persists for wd
    const int t2 = tid * 2;
    float un0 = a_val, un1 = a_val;

    // ---- Sinkhorn loop ----
    for (int it = 0; it < 100; ++it) {
        // v-pass: 4x4 register tile over this thread's 16-float n-chunk
        u64t acc[4][4] = {};
#pragma unroll
        for (int q = 0; q < 8; q++) {
            u64t u2 = *(const u64t*)(ub + 2 * q);
            u64t a0 = mul2(*(const u64t*)(kyb + 0 * 4 * TSTRIDE + 2 * q), u2);
            u64t a1 = mul2(*(const u64t*)(kyb + 1 * 4 * TSTRIDE + 2 * q), u2);
            u64t a2 = mul2(*(const u64t*)(kyb + 2 * 4 * TSTRIDE + 2 * q), u2);
            u64t a3 = mul2(*(const u64t*)(kyb + 3 * 4 * TSTRIDE + 2 * q), u2);
            u64t x0 = *(const u64t*)(kxb + 0 * 4 * TSTRIDE + 2 * q);
            u64t x1 = *(const u64t*)(kxb + 1 * 4 * TSTRIDE + 2 * q);
            u64t x2 = *(const u64t*)(kxb + 2 * 4 * TSTRIDE + 2 * q);
            u64t x3 = *(const u64t*)(kxb + 3 * 4 * TSTRIDE + 2 * q);
            fma2(acc[0][0], a0, x0); fma2(acc[0][1], a0, x1);
            fma2(acc[0][2], a0, x2); fma2(acc[0][3], a0, x3);
            fma2(acc[1][0], a1, x0); fma2(acc[1][1], a1, x1);
            fma2(acc[1][2], a1, x2); fma2(acc[1][3], a1, x3);
            fma2(acc[2][0], a2, x0); fma2(acc[2][1], a2, x1);
            fma2(acc[2][2], a2, x2); fma2(acc[2][3], a2, x3);
            fma2(acc[3][0], a3, x0); fma2(acc[3][1], a3, x1);
            fma2(acc[3][2], a3, x2); fma2(acc[3][3], a3, x3);
        }
        // cross-chunk pre-reduction (hh pair) + store this lane's half
#pragma unroll
        for (int r = 0; r < 4; r++) {
#pragma unroll
            for (int c = 0; c < 4; c++) {
                float f = hsum1(acc[r][c]);
                f += __shfl_xor_sync(0xffffffffu, f, 16);
                if (c == m_off || c == m_off + 1)
                    part[wrp * PSTRIDE + (jg + 4 * r) * 16 + (ig + 4 * c)] = f;
            }
        }
        __syncthreads();

        // combine (all warps): 4 threads/cell, each sums 8 chunk-partials
        {
            float s = ((pbase[0 * PSTRIDE] + pbase[1 * PSTRIDE])
                     + (pbase[2 * PSTRIDE] + pbase[3 * PSTRIDE]))
                    + ((pbase[4 * PSTRIDE] + pbase[5 * PSTRIDE])
                     + (pbase[6 * PSTRIDE] + pbase[7 * PSTRIDE]));
            s += __shfl_xor_sync(0xffffffffu, s, 1);
            s += __shfl_xor_sync(0xffffffffu, s, 2);
            float newv = __fdividef(bsh[cc], s + 1e-16f);
            float oldv = Vs[cc];
            if (it == 2) {
                float v1 = Vm1[cc];
                float d2 = newv - oldv;
                float d1 = oldv - v1;
                float lam = __fdividef(d2, d1);
                if (fabsf(d1) > 1e-30f && lam > 0.0f && lam < 0.95f)
                    newv = newv + __fdividef(d2 * lam, 1.0f - lam);
            }
            if (qd == 0) {
                if (it < 3) Vm1[cc] = oldv;
                Vs[cc] = newv;
            }
            float rd = fabsf(newv - oldv) * __frcp_rn(fabsf(newv) + 1e-30f);
#pragma unroll
            for (int o = 16; o > 0; o >>= 1)
                rd = fmaxf(rd, __shfl_xor_sync(0xffffffffu, rd, o));
            if (lane == 0) red[wrp] = rd;
        }
        __syncthreads();   // Vs + red visible
        if (tid < 32) {
            float m = red[tid];
#pragma unroll
            for (int o = 16; o > 0; o >>= 1)
                m = fmaxf(m, __shfl_xor_sync(0xffffffffu, m, o));
            if (tid == 0 && m < CONV_TOL) s_conv = 1;
        }

        // u-pass: threads 0..511 handle points (2t, 2t+1).
        // z[i] = sum_j ky[j]*V[j][i]; s = sum_i kx[i]*z[i]
        if (tid < 512) {
            u64t zp0[8] = {0,0,0,0,0,0,0,0};
            u64t zp1[8] = {0,0,0,0,0,0,0,0};
#pragma unroll
            for (int j = 0; j < 16; j++) {
                u64t kj2 = *(const u64t*)(KyT + j * TSTRIDE + t2);
                float ky0, ky1; unpack2(kj2, ky0, ky1);
                u64t k0 = pack2(ky0, ky0), k1 = pack2(ky1, ky1);
                const ulonglong2* Vr = (const ulonglong2*)(Vs + j * 16);
                ulonglong2 v0 = Vr[0], v1 = Vr[1], v2 = Vr[2], v3 = Vr[3];
                fma2(zp0[0], k0, v0.x); fma2(zp0[1], k0, v0.y);
                fma2(zp0[2], k0, v1.x); fma2(zp0[3], k0, v1.y);
                fma2(zp0[4], k0, v2.x); fma2(zp0[5], k0, v2.y);
                fma2(zp0[6], k0, v3.x); fma2(zp0[7], k0, v3.y);
                fma2(zp1[0], k1, v0.x); fma2(zp1[1], k1, v0.y);
                fma2(zp1[2], k1, v1.x); fma2(zp1[3], k1, v1.y);
                fma2(zp1[4], k1, v2.x); fma2(zp1[5], k1, v2.y);
                fma2(zp1[6], k1, v3.x); fma2(zp1[7], k1, v3.y);
            }
            u64t sa0 = 0, sb0 = 0, sa1 = 0, sb1 = 0;
#pragma unroll
            for (int p = 0; p < 4; p++) {
                float a0, a1, b0, b1, c0, c1, d0, d1;
                unpack2(*(const u64t*)(KxT + (4 * p + 0) * TSTRIDE + t2), a0, a1);
                unpack2(*(const u64t*)(KxT + (4 * p + 1) * TSTRIDE + t2), b0, b1);
                unpack2(*(const u64t*)(KxT + (4 * p + 2) * TSTRIDE + t2), c0, c1);
                unpack2(*(const u64t*)(KxT + (4 * p + 3) * TSTRIDE + t2), d0, d1);
                fma2(sa0, pack2(a0, b0), zp0[2 * p]);
                fma2(sb0, pack2(c0, d0), zp0[2 * p + 1]);
                fma2(sa1, pack2(a1, b1), zp1[2 * p]);
                fma2(sb1, pack2(c1, d1), zp1[2 * p + 1]);
            }
            un0 = a_val * __frcp_rn(hsum2(sa0, sb0) + 1e-16f);
            un1 = a_val * __frcp_rn(hsum2(sa1, sb1) + 1e-16f);
            *(u64t*)(us + t2) = pack2(un0, un1);
        }
        __syncthreads();   // us visible; s_conv (written pre-barrier) visible
        if (s_conv) break;
    }

    // ---- epilogue part 1: wd, threads 0..511, 2 points each ----
    // wd_n = u_n * [ sum_i kx_i*xdis_i*z_i + sum_i kx_i*zy_i ]
    //   z_i = sum_j ky_j V[j][i],  zy_i = sum_j ky_j*ydis_j V[j][i]
    float wdp = 0.f;
    if (tid < 512) {
        float4 pv = *(const float4*)(pts + img * 2048 + 4 * tid);
        // ---- point 0 ----
        {
            float ppx = pv.x * (2.0f / 256.0f) - 1.0f;
            float ppy = pv.y * (2.0f / 256.0f) - 1.0f;
            u64t zp[8]  = {0,0,0,0,0,0,0,0};
            u64t zyp[8] = {0,0,0,0,0,0,0,0};
#pragma unroll
            for (int j = 0; j < 16; j++) {
                float kyj = KyT[j * TSTRIDE + t2];
                float dy  = ppy - cood[j];
                u64t kj  = pack2(kyj, kyj);
                float kyy = kyj * dy * dy;
                u64t kjy = pack2(kyy, kyy);
                const ulonglong2* Vr = (const ulonglong2*)(Vs + j * 16);
                ulonglong2 v0 = Vr[0], v1 = Vr[1], v2 = Vr[2], v3 = Vr[3];
                fma2(zp[0], kj, v0.x);  fma2(zp[1], kj, v0.y);
                fma2(zp[2], kj, v1.x);  fma2(zp[3], kj, v1.y);
                fma2(zp[4], kj, v2.x);  fma2(zp[5], kj, v2.y);
                fma2(zp[6], kj, v3.x);  fma2(zp[7], kj, v3.y);
                fma2(zyp[0], kjy, v0.x); fma2(zyp[1], kjy, v0.y);
                fma2(zyp[2], kjy, v1.x); fma2(zyp[3], kjy, v1.y);
                fma2(zyp[4], kjy, v2.x); fma2(zyp[5], kjy, v2.y);
                fma2(zyp[6], kjy, v3.x); fma2(zyp[7], kjy, v3.y);
            }
            u64t sa = 0, sb = 0;
#pragma unroll
            for (int p = 0; p < 8; p++) {
                float kx0 = KxT[(2 * p) * TSTRIDE + t2];
                float kx1 = KxT[(2 * p + 1) * TSTRIDE + t2];
                float dx0 = ppx - cood[2 * p];
                float dx1 = ppx - cood[2 * p + 1];
                fma2(sa, pack2(kx0 * dx0 * dx0, kx1 * dx1 * dx1), zp[p]);
                fma2(sb, pack2(kx0, kx1), zyp[p]);
            }
            wdp = un0 * hsum2(sa, sb);
        }
        // ---- point 1 ----
        {
            float ppx = pv.z * (2.0f / 256.0f) - 1.0f;
            float ppy = pv.w * (2.0f / 256.0f) - 1.0f;
            u64t zp[8]  = {0,0,0,0,0,0,0,0};
            u64t zyp[8] = {0,0,0,0,0,0,0,0};
#pragma unroll
            for (int j = 0; j < 16; j++) {
                float kyj = KyT[j * TSTRIDE + t2 + 1];
                float dy  = ppy - cood[j];
                u64t kj  = pack2(kyj, kyj);
                float kyy = kyj * dy * dy;
                u64t kjy = pack2(kyy, kyy);
                const ulonglong2* Vr = (const ulonglong2*)(Vs + j * 16);
                ulonglong2 v0 = Vr[0], v1 = Vr[1], v2 = Vr[2], v3 = Vr[3];
                fma2(zp[0], kj, v0.x);  fma2(zp[1], kj, v0.y);
                fma2(zp[2], kj, v1.x);  fma2(zp[3], kj, v1.y);
                fma2(zp[4], kj, v2.x);  fma2(zp[5], kj, v2.y);
                fma2(zp[6], kj, v3.x);  fma2(zp[7], kj, v3.y);
                fma2(zyp[0], kjy, v0.x); fma2(zyp[1], kjy, v0.y);
                fma2(zyp[2], kjy, v1.x); fma2(zyp[3], kjy, v1.y);
                fma2(zyp[4], kjy, v2.x); fma2(zyp[5], kjy, v2.y);
                fma2(zyp[6], kjy, v3.x); fma2(zyp[7], kjy, v3.y);
            }
            u64t sa = 0, sb = 0;
#pragma unroll
            for (int p = 0; p < 8; p++) {
                float kx0 = KxT[(2 * p) * TSTRIDE + t2 + 1];
                float kx1 = KxT[(2 * p + 1) * TSTRIDE + t2 + 1];
                float dx0 = ppx - cood[2 * p];
                float dx1 = ppx - cood[2 * p + 1];
                fma2(sa, pack2(kx0 * dx0 * dx0, kx1 * dx1 * dx1), zp[p]);
                fma2(sb, pack2(kx0, kx1), zyp[p]);
            }
            wdp += un1 * hsum2(sa, sb);
        }
    }

    // ---- epilogue part 2: ot, sc, S via shuffle reductions ----
    float bt = 0.f, udv = 0.f;
    if (tid < 256) {
        udv = ud[img * 256 + tid];
        bt  = REGP * __logf(Vs[tid] + 1e-16f);      // beta
        float e0 = bsh[tid] * bt;   // -> ot
        float e1 = udv;             // -> sc
        float e2 = udv * bt;        // -> S
#pragma unroll
        for (int o = 16; o > 0; o >>= 1) {
            e0 += __shfl_xor_sync(0xffffffffu, e0, o);
            e1 += __shfl_xor_sync(0xffffffffu, e1, o);
            e2 += __shfl_xor_sync(0xffffffffu, e2, o);
        }
        if (lane == 0) {
            red[wrp]      = e0;   // warps 0..7
            red[8 + wrp]  = e1;
            red[16 + wrp] = e2;
        }
    }
    __syncthreads();
    if (tid < 8) {
        float a0 = red[tid], a1 = red[8 + tid], a2 = red[16 + tid];
#pragma unroll
        for (int o = 4; o > 0; o >>= 1) {
            a0 += __shfl_xor_sync(0x000000ffu, a0, o);
            a1 += __shfl_xor_sync(0x000000ffu, a1, o);
            a2 += __shfl_xor_sync(0x000000ffu, a2, o);
        }
        if (tid == 0) { red[32] = a0; red[33] = a1; red[34] = a2; }
    }
    __syncthreads();
    const float ot = red[32];
    const float sc = red[33];
    const float S  = red[34];
    const float denom = sc * sc + 1e-8f;
    float lv = (tid < 256) ? udv * ((sc / denom) * bt - S / denom) : 0.f;

    // lv + wdp reduction: shuffle within warps, then warp 0 finishes
#pragma unroll
    for (int o = 16; o > 0; o >>= 1) {
        lv  += __shfl_xor_sync(0xffffffffu, lv,  o);
        wdp += __shfl_xor_sync(0xffffffffu, wdp, o);
    }
    if (lane == 0) { part[wrp] = lv; part[32 + wrp] = wdp; }
    __syncthreads();
    if (tid < 32) {
        float l2 = part[tid], w2 = part[32 + tid];
#pragma unroll
        for (int o = 16; o > 0; o >>= 1) {
            l2 += __shfl_xor_sync(0xffffffffu, l2, o);
            w2 += __shfl_xor_sync(0xffffffffu, w2, o);
        }
        if (tid == 0) {
            g_partial[img * 3 + 0] = l2;
            g_partial[img * 3 + 1] = w2;
            g_partial[img * 3 + 2] = ot;
            __threadfence();
            unsigned int old = atomicAdd(&g_ctr, 1u);
            s_last = (old == 127u) ? 1 : 0;
        }
    }
    __syncthreads();

    // last-arriving block reduces the 128 per-image partials (fixed tree)
    if (s_last) {
        if (tid == 0) atomicExch(&g_ctr, 0u);
        __threadfence();
        float r0 = 0.f, r1 = 0.f, r2 = 0.f;
        if (tid < 128) {
            r0 = __ldcg(&g_partial[tid * 3 + 0]);
            r1 = __ldcg(&g_partial[tid * 3 + 1]);
            r2 = __ldcg(&g_partial[tid * 3 + 2]);
#pragma unroll
            for (int o = 16; o > 0; o >>= 1) {
                r0 += __shfl_xor_sync(0xffffffffu, r0, o);
                r1 += __shfl_xor_sync(0xffffffffu, r1, o);
                r2 += __shfl_xor_sync(0xffffffffu, r2, o);
            }
            if (lane == 0) {
                red[wrp] = r0; red[8 + wrp] = r1; red[16 + wrp] = r2;
            }
        }
        __syncthreads();
        if (tid < 4) {
            float a0 = red[tid], a1 = red[8 + tid], a2 = red[16 + tid];
#pragma unroll
            for (int o = 2; o > 0; o >>= 1) {
                a0 += __shfl_xor_sync(0x0000000fu, a0, o);
                a1 += __shfl_xor_sync(0x0000000fu, a1, o);
                a2 += __shfl_xor_sync(0x0000000fu, a2, o);
            }
            if (tid == 0) { out[0] = a0; out[1] = a1; out[2] = a2; }
        }
    }
}

extern "C" void kernel_launch(void* const* d_in, const int* in_sizes, int n_in,
                              void* d_out, int out_size)
{
    const float* nd  = (const float*)d_in[0];
    const float* ud  = (const float*)d_in[1];
    const float* pts = (const float*)d_in[2];

    size_t smem = (size_t)(2 * 16 * TSTRIDE + 1024 + 3 * 256 + 32 * PSTRIDE + 64)
                * sizeof(float);
    cudaFuncSetAttribute(ot_kernel, cudaFuncAttributeMaxDynamicSharedMemorySize, (int)smem);
    ot_kernel<<<128, 1024, smem>>>(nd, ud, pts, (float*)d_out);
}

// round 9
// speedup vs baseline: 2.4167x; 2.4167x over previous
#include <cuda_runtime.h>

// OT_Loss: batched Sinkhorn OT. B=128 images, N=1024 points, 16x16 grid, REG=10.
// Separable: K[n][j*16+i] = Ky[n][j]*Kx[n][i]. One block per image, 1024 threads.
// R9: revert to R7 structure (R8's 2-point u-pass spilled registers -> DRAM
// traffic, 2.4x regression); keep CONV_TOL 5e-3 (validated safe in R8).

#define REGP     10.0f
#define TSTRIDE  1028          // floats; row shift 16B mod 128 per row
#define CONV_TOL 5e-3f
#define RHO      0.99687988f   // exp(-2*D^2/REG), D = 0.125
#define PSTRIDE  257           // partials stride (floats): conflict-free combine

typedef unsigned long long u64t;

__device__ __forceinline__ u64t pack2(float a, float b) {
    u64t r; asm("mov.b64 %0, {%1, %2};" : "=l"(r) : "f"(a), "f"(b)); return r;
}
__device__ __forceinline__ void fma2(u64t& d, u64t a, u64t b) {
    asm("fma.rn.f32x2 %0, %1, %2, %0;" : "+l"(d) : "l"(a), "l"(b));
}
__device__ __forceinline__ u64t mul2(u64t a, u64t b) {
    u64t r; asm("mul.rn.f32x2 %0, %1, %2;" : "=l"(r) : "l"(a), "l"(b)); return r;
}
__device__ __forceinline__ float hsum1(u64t a) {
    float x, y;
    asm("mov.b64 {%0, %1}, %2;" : "=f"(x), "=f"(y) : "l"(a));
    return x + y;
}
__device__ __forceinline__ float hsum2(u64t a, u64t b) {
    float ax, ay, bx, by;
    asm("mov.b64 {%0, %1}, %2;" : "=f"(ax), "=f"(ay) : "l"(a));
    asm("mov.b64 {%0, %1}, %2;" : "=f"(bx), "=f"(by) : "l"(b));
    return (ax + ay) + (bx + by);
}

__device__ float        g_partial[128 * 3];
__device__ unsigned int g_ctr = 0;

__global__ void __launch_bounds__(1024, 1) ot_kernel(
    const float* __restrict__ nd,   // [128,256]
    const float* __restrict__ ud,   // [128,256]
    const float* __restrict__ pts,  // [128,1024,2]
    float* __restrict__ out)        // [3]
{
    extern __shared__ float sm[];
    float* KxT  = sm;                    // [16][TSTRIDE]
    float* KyT  = KxT  + 16 * TSTRIDE;
    float* us   = KyT  + 16 * TSTRIDE;   // [1024]
    float* Vs   = us   + 1024;           // [256]
    float* Vm1  = Vs   + 256;            // [256]
    float* bsh  = Vm1  + 256;            // [256]
    float* part = bsh  + 256;            // [32*PSTRIDE]
    float* red  = part + 32 * PSTRIDE;   // [64]
    __shared__ int s_conv, s_last;

    const int tid  = threadIdx.x;
    const int lane = tid & 31;
    const int wrp  = tid >> 5;
    const int img  = blockIdx.x;
    const float a_val = 1.0f / 1024.0f;

    float cood[16];
#pragma unroll
    for (int i = 0; i < 16; i++)
        cood[i] = (float)(16 * i + 8) * (1.0f / 256.0f) * 2.0f - 1.0f;

    if (tid < 256) { bsh[tid] = nd[img * 256 + tid]; Vs[tid] = 1.0f / 256.0f; }
    if (tid == 0) s_conv = 0;

    // ---- setup: one point per thread; kx/ky by geometric recurrence ----
    const float px = pts[img * 2048 + 2 * tid]     * (2.0f / 256.0f) - 1.0f;
    const float py = pts[img * 2048 + 2 * tid + 1] * (2.0f / 256.0f) - 1.0f;
    float un = a_val;
    us[tid] = a_val;
    {
        float dx0 = px - cood[0];
        float dy0 = py - cood[0];
        float kx = __expf(dx0 * dx0 * (-1.0f / REGP));
        float ky = __expf(dy0 * dy0 * (-1.0f / REGP));
        float rx = __expf((0.25f * dx0 - 0.015625f) * (1.0f / REGP));
        float ry = __expf((0.25f * dy0 - 0.015625f) * (1.0f / REGP));
#pragma unroll
        for (int i = 0; i < 16; i++) {
            KxT[i * TSTRIDE + tid] = kx;
            KyT[i * TSTRIDE + tid] = ky;
            kx *= rx; rx *= RHO;
            ky *= ry; ry *= RHO;
        }
    }
    __syncthreads();

    // v-pass mapping: thread = (hh, jg, ig); 4x4 cells {jg+4r}x{ig+4c},
    // n-chunk hh covers floats [hh*16, hh*16+16). Warp holds hh={2w,2w+1}.
    const int hh = tid >> 4;          // 0..63
    const int jg = (tid >> 2) & 3;    // 0..3
    const int ig = tid & 3;           // 0..3
    const float* kyb = KyT + jg * TSTRIDE + hh * 16;
    const float* kxb = KxT + ig * TSTRIDE + hh * 16;
    const float* ub  = us + hh * 16;
    const int m_off  = ((tid >> 4) & 1) * 2;   // which c-pair this lane stores

    // combine-phase mapping: 4 threads per cell; each sums 8 of 32 chunk-partials
    const int cc = tid >> 2, qd = tid & 3;
    const float* pbase = part + qd * 8 * PSTRIDE + cc;

    u64t zp[8];   // persists: last u-pass's z_i pairs, reused in wd epilogue

    // ---- Sinkhorn loop ----
    for (int it = 0; it < 100; ++it) {
        // v-pass: 4x4 register tile over this thread's 16-float n-chunk
        u64t acc[4][4] = {};
#pragma unroll
        for (int q = 0; q < 8; q++) {
            u64t u2 = *(const u64t*)(ub + 2 * q);
            u64t a0 = mul2(*(const u64t*)(kyb + 0 * 4 * TSTRIDE + 2 * q), u2);
            u64t a1 = mul2(*(const u64t*)(kyb + 1 * 4 * TSTRIDE + 2 * q), u2);
            u64t a2 = mul2(*(const u64t*)(kyb + 2 * 4 * TSTRIDE + 2 * q), u2);
            u64t a3 = mul2(*(const u64t*)(kyb + 3 * 4 * TSTRIDE + 2 * q), u2);
            u64t x0 = *(const u64t*)(kxb + 0 * 4 * TSTRIDE + 2 * q);
            u64t x1 = *(const u64t*)(kxb + 1 * 4 * TSTRIDE + 2 * q);
            u64t x2 = *(const u64t*)(kxb + 2 * 4 * TSTRIDE + 2 * q);
            u64t x3 = *(const u64t*)(kxb + 3 * 4 * TSTRIDE + 2 * q);
            fma2(acc[0][0], a0, x0); fma2(acc[0][1], a0, x1);
            fma2(acc[0][2], a0, x2); fma2(acc[0][3], a0, x3);
            fma2(acc[1][0], a1, x0); fma2(acc[1][1], a1, x1);
            fma2(acc[1][2], a1, x2); fma2(acc[1][3], a1, x3);
            fma2(acc[2][0], a2, x0); fma2(acc[2][1], a2, x1);
            fma2(acc[2][2], a2, x2); fma2(acc[2][3], a2, x3);
            fma2(acc[3][0], a3, x0); fma2(acc[3][1], a3, x1);
            fma2(acc[3][2], a3, x2); fma2(acc[3][3], a3, x3);
        }
        // cross-chunk pre-reduction (hh pair) + store this lane's half
#pragma unroll
        for (int r = 0; r < 4; r++) {
#pragma unroll
            for (int c = 0; c < 4; c++) {
                float f = hsum1(acc[r][c]);
                f += __shfl_xor_sync(0xffffffffu, f, 16);
                if (c == m_off || c == m_off + 1)
                    part[wrp * PSTRIDE + (jg + 4 * r) * 16 + (ig + 4 * c)] = f;
            }
        }
        __syncthreads();

        // combine (all warps): 4 threads/cell, each sums 8 chunk-partials
        {
            float s = ((pbase[0 * PSTRIDE] + pbase[1 * PSTRIDE])
                     + (pbase[2 * PSTRIDE] + pbase[3 * PSTRIDE]))
                    + ((pbase[4 * PSTRIDE] + pbase[5 * PSTRIDE])
                     + (pbase[6 * PSTRIDE] + pbase[7 * PSTRIDE]));
            s += __shfl_xor_sync(0xffffffffu, s, 1);
            s += __shfl_xor_sync(0xffffffffu, s, 2);
            float newv = __fdividef(bsh[cc], s + 1e-16f);
            float oldv = Vs[cc];
            if (it == 2) {
                float v1 = Vm1[cc];
                float d2 = newv - oldv;
                float d1 = oldv - v1;
                float lam = __fdividef(d2, d1);
                if (fabsf(d1) > 1e-30f && lam > 0.0f && lam < 0.95f)
                    newv = newv + __fdividef(d2 * lam, 1.0f - lam);
            }
            if (qd == 0) {
                if (it < 3) Vm1[cc] = oldv;
                Vs[cc] = newv;
            }
            float rd = fabsf(newv - oldv) * __frcp_rn(fabsf(newv) + 1e-30f);
#pragma unroll
            for (int o = 16; o > 0; o >>= 1)
                rd = fmaxf(rd, __shfl_xor_sync(0xffffffffu, rd, o));
            if (lane == 0) red[wrp] = rd;
        }
        __syncthreads();   // Vs + red visible
        if (tid < 32) {
            float m = red[tid];
#pragma unroll
            for (int o = 16; o > 0; o >>= 1)
                m = fmaxf(m, __shfl_xor_sync(0xffffffffu, m, o));
            if (tid == 0 && m < CONV_TOL) s_conv = 1;
        }

        // u-pass: z[i] = sum_j ky[j]*V[j][i]; s = sum_i kx[i]*z[i]
        {
            float ky[16];
#pragma unroll
            for (int i = 0; i < 16; i++) ky[i] = KyT[i * TSTRIDE + tid];
#pragma unroll
            for (int p = 0; p < 8; p++) zp[p] = 0;
#pragma unroll
            for (int j = 0; j < 16; j++) {
                u64t kj = pack2(ky[j], ky[j]);
                const ulonglong2* Vr = (const ulonglong2*)(Vs + j * 16);
                ulonglong2 v0 = Vr[0], v1 = Vr[1], v2 = Vr[2], v3 = Vr[3];
                fma2(zp[0], kj, v0.x); fma2(zp[1], kj, v0.y);
                fma2(zp[2], kj, v1.x); fma2(zp[3], kj, v1.y);
                fma2(zp[4], kj, v2.x); fma2(zp[5], kj, v2.y);
                fma2(zp[6], kj, v3.x); fma2(zp[7], kj, v3.y);
            }
            u64t sa = 0, sb = 0;
#pragma unroll
            for (int p = 0; p < 4; p++) {
                float kxa = KxT[(4 * p + 0) * TSTRIDE + tid];
                float kxb2 = KxT[(4 * p + 1) * TSTRIDE + tid];
                float kxc = KxT[(4 * p + 2) * TSTRIDE + tid];
                float kxd = KxT[(4 * p + 3) * TSTRIDE + tid];
                fma2(sa, pack2(kxa, kxb2), zp[2 * p]);
                fma2(sb, pack2(kxc, kxd), zp[2 * p + 1]);
            }
            float s = hsum2(sa, sb);
            un = a_val * __frcp_rn(s + 1e-16f);
            us[tid] = un;
        }
        __syncthreads();   // us visible; s_conv (written pre-barrier) visible
        if (s_conv) break;
    }

    // ---- epilogue part 1: wd (uses zp from the final u-pass) ----
    float wdp;
    {
        float ky[16];
#pragma unroll
        for (int i = 0; i < 16; i++) ky[i] = KyT[i * TSTRIDE + tid];
        u64t zyp[8] = {0, 0, 0, 0, 0, 0, 0, 0};
#pragma unroll
        for (int j = 0; j < 16; j++) {
            float dy = py - cood[j];
            float kyy = ky[j] * dy * dy;
            u64t kjy = pack2(kyy, kyy);
            const ulonglong2* Vr = (const ulonglong2*)(Vs + j * 16);
            ulonglong2 v0 = Vr[0], v1 = Vr[1], v2 = Vr[2], v3 = Vr[3];
            fma2(zyp[0], kjy, v0.x); fma2(zyp[1], kjy, v0.y);
            fma2(zyp[2], kjy, v1.x); fma2(zyp[3], kjy, v1.y);
            fma2(zyp[4], kjy, v2.x); fma2(zyp[5], kjy, v2.y);
            fma2(zyp[6], kjy, v3.x); fma2(zyp[7], kjy, v3.y);
        }
        u64t sa = 0, sb = 0;
#pragma unroll
        for (int p = 0; p < 8; p++) {
            float kx0 = KxT[(2 * p) * TSTRIDE + tid];
            float kx1 = KxT[(2 * p + 1) * TSTRIDE + tid];
            float dx0 = px - cood[2 * p];
            float dx1 = px - cood[2 * p + 1];
            fma2(sa, pack2(kx0 * dx0 * dx0, kx1 * dx1 * dx1), zp[p]);
            fma2(sb, pack2(kx0, kx1), zyp[p]);
        }
        wdp = un * hsum2(sa, sb);
    }

    // ---- epilogue part 2: ot, sc, S via shuffle reductions ----
    float bt = 0.f, udv = 0.f;
    float e0 = 0.f, e1 = 0.f, e2 = 0.f;
    if (tid < 256) {
        udv = ud[img * 256 + tid];
        bt  = REGP * __logf(Vs[tid] + 1e-16f);      // beta
        e0 = bsh[tid] * bt;   // -> ot
        e1 = udv;             // -> sc
        e2 = udv * bt;        // -> S
#pragma unroll
        for (int o = 16; o > 0; o >>= 1) {
            e0 += __shfl_xor_sync(0xffffffffu, e0, o);
            e1 += __shfl_xor_sync(0xffffffffu, e1, o);
            e2 += __shfl_xor_sync(0xffffffffu, e2, o);
        }
        if (lane == 0) {
            red[wrp]      = e0;   // warps 0..7
            red[8 + wrp]  = e1;
            red[16 + wrp] = e2;
        }
    }
    __syncthreads();
    if (tid < 8) {
        float a0 = red[tid], a1 = red[8 + tid], a2 = red[16 + tid];
#pragma unroll
        for (int o = 4; o > 0; o >>= 1) {
            a0 += __shfl_xor_sync(0x000000ffu, a0, o);
            a1 += __shfl_xor_sync(0x000000ffu, a1, o);
            a2 += __shfl_xor_sync(0x000000ffu, a2, o);
        }
        if (tid == 0) { red[32] = a0; red[33] = a1; red[34] = a2; }
    }
    __syncthreads();
    const float ot = red[32];
    const float sc = red[33];
    const float S  = red[34];
    const float denom = sc * sc + 1e-8f;
    float lv = (tid < 256) ? udv * ((sc / denom) * bt - S / denom) : 0.f;

    // lv + wdp reduction: shuffle within warps, then warp 0 finishes
#pragma unroll
    for (int o = 16; o > 0; o >>= 1) {
        lv  += __shfl_xor_sync(0xffffffffu, lv,  o);
        wdp += __shfl_xor_sync(0xffffffffu, wdp, o);
    }
    if (lane == 0) { part[wrp] = lv; part[32 + wrp] = wdp; }
    __syncthreads();
    if (tid < 32) {
        float l2 = part[tid], w2 = part[32 + tid];
#pragma unroll
        for (int o = 16; o > 0; o >>= 1) {
            l2 += __shfl_xor_sync(0xffffffffu, l2, o);
            w2 += __shfl_xor_sync(0xffffffffu, w2, o);
        }
        if (tid == 0) {
            g_partial[img * 3 + 0] = l2;
            g_partial[img * 3 + 1] = w2;
            g_partial[img * 3 + 2] = ot;
            __threadfence();
            unsigned int old = atomicAdd(&g_ctr, 1u);
            s_last = (old == 127u) ? 1 : 0;
        }
    }
    __syncthreads();

    // last-arriving block reduces the 128 per-image partials (fixed tree)
    if (s_last) {
        if (tid == 0) atomicExch(&g_ctr, 0u);
        __threadfence();
        float r0 = 0.f, r1 = 0.f, r2 = 0.f;
        if (tid < 128) {
            r0 = __ldcg(&g_partial[tid * 3 + 0]);
            r1 = __ldcg(&g_partial[tid * 3 + 1]);
            r2 = __ldcg(&g_partial[tid * 3 + 2]);
#pragma unroll
            for (int o = 16; o > 0; o >>= 1) {
                r0 += __shfl_xor_sync(0xffffffffu, r0, o);
                r1 += __shfl_xor_sync(0xffffffffu, r1, o);
                r2 += __shfl_xor_sync(0xffffffffu, r2, o);
            }
            if (lane == 0) {
                red[wrp] = r0; red[8 + wrp] = r1; red[16 + wrp] = r2;
            }
        }
        __syncthreads();
        if (tid < 4) {
            float a0 = red[tid], a1 = red[8 + tid], a2 = red[16 + tid];
#pragma unroll
            for (int o = 2; o > 0; o >>= 1) {
                a0 += __shfl_xor_sync(0x0000000fu, a0, o);
                a1 += __shfl_xor_sync(0x0000000fu, a1, o);
                a2 += __shfl_xor_sync(0x0000000fu, a2, o);
            }
            if (tid == 0) { out[0] = a0; out[1] = a1; out[2] = a2; }
        }
    }
}

extern "C" void kernel_launch(void* const* d_in, const int* in_sizes, int n_in,
                              void* d_out, int out_size)
{
    const float* nd  = (const float*)d_in[0];
    const float* ud  = (const float*)d_in[1];
    const float* pts = (const float*)d_in[2];

    size_t smem = (size_t)(2 * 16 * TSTRIDE + 1024 + 3 * 256 + 32 * PSTRIDE + 64)
                * sizeof(float);
    cudaFuncSetAttribute(ot_kernel, cudaFuncAttributeMaxDynamicSharedMemorySize, (int)smem);
    ot_kernel<<<128, 1024, smem>>>(nd, ud, pts, (float*)d_out);
}